// round 7
// baseline (speedup 1.0000x reference)
#include <cuda_runtime.h>
#include <cstdint>
#include <cstddef>

typedef unsigned long long ull;

#define BATCH   32
#define T_STEPS 2048
#define HID     256
#define BT      (BATCH * T_STEPS)         // 65536
#define GCOLS   768                       // [r(256) | z(256) | n(256)] input-side gates

// Scratch for input-side projections (static, no cudaMalloc)
__device__ float g_xproj[(size_t)BT * GCOLS];

// ---------------------------------------------------------------------------
// helpers
// ---------------------------------------------------------------------------
__device__ __forceinline__ void ffma2(ull& d, ull a, ull b) {
    asm("fma.rn.f32x2 %0, %1, %2, %0;" : "+l"(d) : "l"(a), "l"(b));
}

__device__ __forceinline__ float tanh_fast(float x) {
    float y;
    asm("tanh.approx.f32 %0, %1;" : "=f"(y) : "f"(x));
    return y;
}

__device__ __forceinline__ float sigmoid_fast(float x) {
    return fmaf(0.5f, tanh_fast(0.5f * x), 0.5f);
}

// plain remote (cluster) 8-byte store — primitive proven in the R1 passing kernel
__device__ __forceinline__ void st_cluster_b64(uint32_t laddr, uint32_t rank, ull v) {
    uint32_t ra;
    asm volatile("mapa.shared::cluster.u32 %0, %1, %2;" : "=r"(ra) : "r"(laddr), "r"(rank));
    asm volatile("st.shared::cluster.b64 [%0], %1;" :: "r"(ra), "l"(v) : "memory");
}

// release-arrive on a peer CTA's mbarrier (orders this thread's prior remote stores)
__device__ __forceinline__ void mbar_arrive_cluster(uint32_t lmbar, uint32_t rank) {
    uint32_t rm;
    asm volatile("mapa.shared::cluster.u32 %0, %1, %2;" : "=r"(rm) : "r"(lmbar), "r"(rank));
    asm volatile("mbarrier.arrive.release.cluster.shared::cluster.b64 _, [%0];"
                 :: "r"(rm) : "memory");
}

__device__ __forceinline__ void mbar_init(uint32_t mbar, uint32_t count) {
    asm volatile("mbarrier.init.shared.b64 [%0], %1;" :: "r"(mbar), "r"(count) : "memory");
}

__device__ __forceinline__ void mbar_wait_cluster(uint32_t mbar, uint32_t parity) {
    uint32_t done;
    asm volatile(
        "{\n\t.reg .pred p;\n\t"
        "mbarrier.try_wait.parity.acquire.cluster.shared::cta.b64 p, [%1], %2;\n\t"
        "selp.b32 %0, 1, 0, p;\n\t}"
        : "=r"(done) : "r"(mbar), "r"(parity) : "memory");
    while (!done) {
        asm volatile(
            "{\n\t.reg .pred p;\n\t"
            "mbarrier.try_wait.parity.acquire.cluster.shared::cta.b64 p, [%1], %2, 0x989680;\n\t"
            "selp.b32 %0, 1, 0, p;\n\t}"
            : "=r"(done) : "r"(mbar), "r"(parity) : "memory");
    }
}

// ---------------------------------------------------------------------------
// Kernel 1: input projection GEMM  (unchanged — measured OK)
// ---------------------------------------------------------------------------
#define PROJ_SMEM_BYTES ((64*256 + 128*260) * 4)

__global__ void __launch_bounds__(128, 1) proj_kernel(
    const float* __restrict__ x,
    const float* __restrict__ W_irz, const float* __restrict__ b_irz,
    const float* __restrict__ W_in,  const float* __restrict__ b_in)
{
    extern __shared__ float smem[];
    float* As = smem;
    float* Bs = smem + 64 * 256;

    const int tid = threadIdx.x;
    const int m0 = blockIdx.x * 64;
    const int n0 = blockIdx.y * 128;

    const float* Wsrc; const float* bsrc;
    if (n0 < 512) { Wsrc = W_irz + (size_t)n0 * 256;         bsrc = b_irz + n0; }
    else          { Wsrc = W_in  + (size_t)(n0 - 512) * 256; bsrc = b_in + (n0 - 512); }

    {
        const float4* xg = (const float4*)(x + (size_t)m0 * 256);
        float4* As4 = (float4*)As;
        #pragma unroll
        for (int it = 0; it < 32; it++) {
            int idx = it * 128 + tid;
            As4[idx] = xg[idx];
        }
        const float4* wg = (const float4*)Wsrc;
        #pragma unroll
        for (int it = 0; it < 64; it++) {
            int idx = it * 128 + tid;
            int n = idx >> 6, k4 = idx & 63;
            *(float4*)(Bs + n * 260 + (k4 << 2)) = wg[idx];
        }
    }
    __syncthreads();

    const int lane = tid & 31, warp = tid >> 5;
    const int cg = lane & 15;
    const int rg2 = lane >> 4;
    const int rglob = warp * 2 + rg2;

    ull acc[64];
    #pragma unroll
    for (int i = 0; i < 64; i++) acc[i] = 0ull;

    const ull* Au = (const ull*)As;
    const ull* Bu = (const ull*)Bs;

    int aoff[8], boff[8];
    #pragma unroll
    for (int i = 0; i < 8; i++) aoff[i] = (rglob + 8 * i) * 128;
    #pragma unroll
    for (int j = 0; j < 8; j++) boff[j] = (cg + 16 * j) * 130;

    #pragma unroll 2
    for (int kk = 0; kk < 128; kk++) {
        ull a2[8], b2[8];
        #pragma unroll
        for (int i = 0; i < 8; i++) a2[i] = Au[aoff[i] + kk];
        #pragma unroll
        for (int j = 0; j < 8; j++) b2[j] = Bu[boff[j] + kk];
        #pragma unroll
        for (int i = 0; i < 8; i++)
            #pragma unroll
            for (int j = 0; j < 8; j++)
                ffma2(acc[i * 8 + j], a2[i], b2[j]);
    }

    float bias[8];
    #pragma unroll
    for (int j = 0; j < 8; j++) bias[j] = bsrc[cg + 16 * j];

    #pragma unroll
    for (int i = 0; i < 8; i++) {
        int m = rglob + 8 * i;
        float* orow = g_xproj + (size_t)(m0 + m) * GCOLS + n0;
        #pragma unroll
        for (int j = 0; j < 8; j++) {
            union { ull u; float f[2]; } v; v.u = acc[i * 8 + j];
            orow[cg + 16 * j] = v.f[0] + v.f[1] + bias[j];
        }
    }
}

// ---------------------------------------------------------------------------
// Kernel 2: persistent GRU recurrence.
// Cluster of 4 CTAs per batch (grid 128, block 384). Thread = (row ro, half hf):
// 192 gate rows x 2 k-halves, weights register-resident (64 ull/thread).
// Sync: per h buffer, an mbarrier with count=128 (auto-reload). Senders do
// plain st.shared::cluster.b64 (pair-packed) then mbarrier.arrive.release on
// each peer; consumers try_wait.parity.acquire — no cluster barrier in loop.
// ---------------------------------------------------------------------------
__global__ void __cluster_dims__(4, 1, 1) __launch_bounds__(384, 1)
gru_kernel(const float* __restrict__ h0,
           const float* __restrict__ W_hrz, const float* __restrict__ b_hrz,
           const float* __restrict__ W_hn,  const float* __restrict__ b_hn,
           float* __restrict__ out, int write_hn)
{
    __shared__ __align__(16) float hbuf[2][HID];   // hbuf[1] = hbuf[0] + 1024 B
    __shared__ float gsum[2][192];
    __shared__ __align__(8) ull mbar[2];           // mbar[1] = mbar[0] + 8 B

    const int tid  = threadIdx.x;
    const int b    = blockIdx.x >> 2;
    const int rank = blockIdx.x & 3;
    const int j0   = rank * 64;
    const int ro   = tid >> 1;    // gate-row 0..191
    const int hf   = tid & 1;     // k-half

    // ---- register-resident weights: 128 floats = 64 packed f32x2 ----
    ull w[64];
    {
        const float* src;
        if (ro < 64)       src = W_hrz + (size_t)(j0 + ro) * 256;
        else if (ro < 128) src = W_hrz + (size_t)(256 + j0 + (ro - 64)) * 256;
        else               src = W_hn  + (size_t)(j0 + (ro - 128)) * 256;
        const ull* ws = (const ull*)src + hf * 64;
        #pragma unroll
        for (int i = 0; i < 64; i++) w[i] = ws[i];
    }

    float bhr = 0.f, bhz = 0.f, bhn = 0.f;
    if (tid < 64) {
        bhr = b_hrz[j0 + tid];
        bhz = b_hrz[256 + j0 + tid];
        bhn = b_hn[j0 + tid];
    }
    if (tid < HID) hbuf[0][tid] = h0[(size_t)b * HID + tid];

    const uint32_t mb0 = (uint32_t)__cvta_generic_to_shared(&mbar[0]);
    if (tid == 0) {
        mbar_init(mb0, 128);        // 4 CTAs x 32 senders per phase; auto-reload
        mbar_init(mb0 + 8, 128);
    }
    __syncthreads();
    asm volatile("barrier.cluster.arrive.aligned;" ::: "memory");
    asm volatile("barrier.cluster.wait.aligned;"  ::: "memory");

    const float* xbase = g_xproj + (size_t)b * T_STEPS * GCOLS;
    float* obase = out + (size_t)b * T_STEPS * HID;

    const uint32_t hb0 = (uint32_t)__cvta_generic_to_shared(&hbuf[0][0]);

    // x-side gate inputs for t=0 (epilogue threads only)
    float xr = 0.f, xz = 0.f, xn = 0.f;
    if (tid < 64) {
        xr = xbase[j0 + tid];
        xz = xbase[256 + j0 + tid];
        xn = xbase[512 + j0 + tid];
    }

    int ph0 = 0, ph1 = 0;

    for (int t = 0; t < T_STEPS; t++) {
        const int par = t & 1;

        // ---- wait for this buffer's h to be fully delivered (t=0: local h0) ----
        if (t > 0) {
            if (par) { mbar_wait_cluster(mb0 + 8, ph1); ph1 ^= 1; }
            else     { mbar_wait_cluster(mb0,     ph0); ph0 ^= 1; }
        }

        // ---- matvec: this thread's 128-k half of its gate row ----
        ull acc0 = 0ull, acc1 = 0ull;
        const float4* h4 = (const float4*)hbuf[par] + hf * 32;
        #pragma unroll
        for (int i = 0; i < 32; i++) {
            union { float4 f; ull u[2]; } hv;
            hv.f = h4[i];
            ffma2(acc0, w[2 * i],     hv.u[0]);
            ffma2(acc1, w[2 * i + 1], hv.u[1]);
        }
        union { ull u; float f[2]; } ua, ub;
        ua.u = acc0; ub.u = acc1;
        float s = (ua.f[0] + ua.f[1]) + (ub.f[0] + ub.f[1]);
        s += __shfl_xor_sync(0xffffffffu, s, 1);   // combine the two k-halves
        if (hf == 0) gsum[par][ro] = s;

        // prefetch next step's x while others compute (epilogue threads only)
        float nxr = xr, nxz = xz, nxn = xn;
        if (tid < 64) {
            const int tn = (t + 1 < T_STEPS) ? (t + 1) : (T_STEPS - 1);
            const float* p = xbase + (size_t)tn * GCOLS;
            nxr = p[j0 + tid]; nxz = p[256 + j0 + tid]; nxn = p[512 + j0 + tid];
        }
        __syncthreads();

        // ---- epilogue: 64 threads finalize their hidden units ----
        if (tid < 64) {
            const int j = tid;
            float r = sigmoid_fast(gsum[par][j]      + bhr + xr);
            float z = sigmoid_fast(gsum[par][64 + j] + bhz + xz);
            float n = tanh_fast(fmaf(r, gsum[par][128 + j] + bhn, xn));
            float hold = hbuf[par][j0 + j];
            float hnew = fmaf(z, hold - n, n);      // (1-z)*n + z*h

            obase[(size_t)t * HID + j0 + j] = hnew;
            if (write_hn && t == T_STEPS - 1)
                out[(size_t)BATCH * T_STEPS * HID + (size_t)b * HID + j0 + j] = hnew;

            // pack (even, odd) unit pair; even threads ship to all 4 CTAs
            float hp = __shfl_xor_sync(0xffffffffu, hnew, 1);
            if ((j & 1) == 0) {
                union { float f[2]; ull u; } pk;
                pk.f[0] = hnew; pk.f[1] = hp;
                const uint32_t po = (uint32_t)(par ^ 1);
                uint32_t laddr = hb0 + po * 1024u + (uint32_t)(j0 + j) * 4u;
                uint32_t lmbar = mb0 + po * 8u;
                st_cluster_b64(laddr, 0u, pk.u);
                st_cluster_b64(laddr, 1u, pk.u);
                st_cluster_b64(laddr, 2u, pk.u);
                st_cluster_b64(laddr, 3u, pk.u);
                mbar_arrive_cluster(lmbar, 0u);
                mbar_arrive_cluster(lmbar, 1u);
                mbar_arrive_cluster(lmbar, 2u);
                mbar_arrive_cluster(lmbar, 3u);
            }
            xr = nxr; xz = nxz; xn = nxn;
        }
    }

    // keep smem alive until all cluster traffic has landed everywhere
    asm volatile("barrier.cluster.arrive.aligned;" ::: "memory");
    asm volatile("barrier.cluster.wait.aligned;"  ::: "memory");
}

// ---------------------------------------------------------------------------
// launch
// ---------------------------------------------------------------------------
extern "C" void kernel_launch(void* const* d_in, const int* in_sizes, int n_in,
                              void* d_out, int out_size)
{
    (void)in_sizes; (void)n_in;
    const float* x     = (const float*)d_in[0];
    const float* h0    = (const float*)d_in[1];
    const float* W_irz = (const float*)d_in[2];
    const float* b_irz = (const float*)d_in[3];
    const float* W_hrz = (const float*)d_in[4];
    const float* b_hrz = (const float*)d_in[5];
    const float* W_in  = (const float*)d_in[6];
    const float* b_in  = (const float*)d_in[7];
    const float* W_hn  = (const float*)d_in[8];
    const float* b_hn  = (const float*)d_in[9];
    float* out = (float*)d_out;

    cudaFuncSetAttribute(proj_kernel, cudaFuncAttributeMaxDynamicSharedMemorySize,
                         PROJ_SMEM_BYTES);
    cudaFuncSetAttribute(gru_kernel, cudaFuncAttributeNonPortableClusterSizeAllowed, 1);

    proj_kernel<<<dim3(BT / 64, GCOLS / 128, 1), 128, PROJ_SMEM_BYTES>>>(
        x, W_irz, b_irz, W_in, b_in);

    const long long need_hn = (long long)BATCH * T_STEPS * HID + (long long)BATCH * HID;
    int write_hn = ((long long)out_size >= need_hn) ? 1 : 0;
    gru_kernel<<<BATCH * 4, 384>>>(h0, W_hrz, b_hrz, W_hn, b_hn, out, write_hn);
}

// round 8
// speedup vs baseline: 1.4355x; 1.4355x over previous
#include <cuda_runtime.h>
#include <cstdint>
#include <cstddef>

typedef unsigned long long ull;

#define BATCH   32
#define T_STEPS 2048
#define HID     256
#define BT      (BATCH * T_STEPS)         // 65536
#define GCOLS   768                       // [r(256) | z(256) | n(256)] input-side gates

// Scratch for input-side projections (static, no cudaMalloc)
__device__ float g_xproj[(size_t)BT * GCOLS];

// ---------------------------------------------------------------------------
// helpers
// ---------------------------------------------------------------------------
__device__ __forceinline__ void ffma2(ull& d, ull a, ull b) {
    asm("fma.rn.f32x2 %0, %1, %2, %0;" : "+l"(d) : "l"(a), "l"(b));
}

__device__ __forceinline__ float tanh_fast(float x) {
    float y;
    asm("tanh.approx.f32 %0, %1;" : "=f"(y) : "f"(x));
    return y;
}

__device__ __forceinline__ float sigmoid_fast(float x) {
    return fmaf(0.5f, tanh_fast(0.5f * x), 0.5f);
}

// plain remote (cluster) 8-byte store — proven primitive on this harness
__device__ __forceinline__ void st_cluster_b64(uint32_t laddr, uint32_t rank, ull v) {
    uint32_t ra;
    asm volatile("mapa.shared::cluster.u32 %0, %1, %2;" : "=r"(ra) : "r"(laddr), "r"(rank));
    asm volatile("st.shared::cluster.b64 [%0], %1;" :: "r"(ra), "l"(v) : "memory");
}

// ---------------------------------------------------------------------------
// Kernel 1: input projection GEMM  (unchanged — measured OK)
// ---------------------------------------------------------------------------
#define PROJ_SMEM_BYTES ((64*256 + 128*260) * 4)

__global__ void __launch_bounds__(128, 1) proj_kernel(
    const float* __restrict__ x,
    const float* __restrict__ W_irz, const float* __restrict__ b_irz,
    const float* __restrict__ W_in,  const float* __restrict__ b_in)
{
    extern __shared__ float smem[];
    float* As = smem;
    float* Bs = smem + 64 * 256;

    const int tid = threadIdx.x;
    const int m0 = blockIdx.x * 64;
    const int n0 = blockIdx.y * 128;

    const float* Wsrc; const float* bsrc;
    if (n0 < 512) { Wsrc = W_irz + (size_t)n0 * 256;         bsrc = b_irz + n0; }
    else          { Wsrc = W_in  + (size_t)(n0 - 512) * 256; bsrc = b_in + (n0 - 512); }

    {
        const float4* xg = (const float4*)(x + (size_t)m0 * 256);
        float4* As4 = (float4*)As;
        #pragma unroll
        for (int it = 0; it < 32; it++) {
            int idx = it * 128 + tid;
            As4[idx] = xg[idx];
        }
        const float4* wg = (const float4*)Wsrc;
        #pragma unroll
        for (int it = 0; it < 64; it++) {
            int idx = it * 128 + tid;
            int n = idx >> 6, k4 = idx & 63;
            *(float4*)(Bs + n * 260 + (k4 << 2)) = wg[idx];
        }
    }
    __syncthreads();

    const int lane = tid & 31, warp = tid >> 5;
    const int cg = lane & 15;
    const int rg2 = lane >> 4;
    const int rglob = warp * 2 + rg2;

    ull acc[64];
    #pragma unroll
    for (int i = 0; i < 64; i++) acc[i] = 0ull;

    const ull* Au = (const ull*)As;
    const ull* Bu = (const ull*)Bs;

    int aoff[8], boff[8];
    #pragma unroll
    for (int i = 0; i < 8; i++) aoff[i] = (rglob + 8 * i) * 128;
    #pragma unroll
    for (int j = 0; j < 8; j++) boff[j] = (cg + 16 * j) * 130;

    #pragma unroll 2
    for (int kk = 0; kk < 128; kk++) {
        ull a2[8], b2[8];
        #pragma unroll
        for (int i = 0; i < 8; i++) a2[i] = Au[aoff[i] + kk];
        #pragma unroll
        for (int j = 0; j < 8; j++) b2[j] = Bu[boff[j] + kk];
        #pragma unroll
        for (int i = 0; i < 8; i++)
            #pragma unroll
            for (int j = 0; j < 8; j++)
                ffma2(acc[i * 8 + j], a2[i], b2[j]);
    }

    float bias[8];
    #pragma unroll
    for (int j = 0; j < 8; j++) bias[j] = bsrc[cg + 16 * j];

    #pragma unroll
    for (int i = 0; i < 8; i++) {
        int m = rglob + 8 * i;
        float* orow = g_xproj + (size_t)(m0 + m) * GCOLS + n0;
        #pragma unroll
        for (int j = 0; j < 8; j++) {
            union { ull u; float f[2]; } v; v.u = acc[i * 8 + j];
            orow[cg + 16 * j] = v.f[0] + v.f[1] + bias[j];
        }
    }
}

// ---------------------------------------------------------------------------
// Kernel 2: persistent GRU recurrence — R1 skeleton (measured best) with:
//   * tanh.approx epilogue
//   * pair-packed remote sends, fan-out depth 2 (even tid -> ranks 0,1;
//     odd tid -> ranks 2,3)
//   * out-STG and x-prefetch moved AFTER barrier.arrive (out of the
//     release set, into the barrier-wait shadow)
// Cluster of 4 CTAs per batch (grid 128, block 384). Thread = (row ro,
// half hf); weights register-resident (64 ull/thread).
// ---------------------------------------------------------------------------
__global__ void __cluster_dims__(4, 1, 1) __launch_bounds__(384, 1)
gru_kernel(const float* __restrict__ h0,
           const float* __restrict__ W_hrz, const float* __restrict__ b_hrz,
           const float* __restrict__ W_hn,  const float* __restrict__ b_hn,
           float* __restrict__ out, int write_hn)
{
    __shared__ __align__(16) float hbuf[2][HID];   // hbuf[1] = hbuf[0] + 1024 B
    __shared__ float gsum[192];

    const int tid  = threadIdx.x;
    const int b    = blockIdx.x >> 2;
    const int rank = blockIdx.x & 3;
    const int j0   = rank * 64;
    const int ro   = tid >> 1;    // gate-row 0..191
    const int hf   = tid & 1;     // k-half

    // ---- register-resident weights: 128 floats = 64 packed f32x2 ----
    ull w[64];
    {
        const float* src;
        if (ro < 64)       src = W_hrz + (size_t)(j0 + ro) * 256;
        else if (ro < 128) src = W_hrz + (size_t)(256 + j0 + (ro - 64)) * 256;
        else               src = W_hn  + (size_t)(j0 + (ro - 128)) * 256;
        const ull* ws = (const ull*)src + hf * 64;
        #pragma unroll
        for (int i = 0; i < 64; i++) w[i] = ws[i];
    }

    float bhr = 0.f, bhz = 0.f, bhn = 0.f;
    if (tid < 64) {
        bhr = b_hrz[j0 + tid];
        bhz = b_hrz[256 + j0 + tid];
        bhn = b_hn[j0 + tid];
    }
    if (tid < HID) hbuf[0][tid] = h0[(size_t)b * HID + tid];
    __syncthreads();
    asm volatile("barrier.cluster.arrive.aligned;" ::: "memory");
    asm volatile("barrier.cluster.wait.aligned;"  ::: "memory");

    const float* xbase = g_xproj + (size_t)b * T_STEPS * GCOLS;
    float* obase = out + (size_t)b * T_STEPS * HID;

    const uint32_t hb0 = (uint32_t)__cvta_generic_to_shared(&hbuf[0][0]);

    // x-side gate inputs for t=0 (epilogue threads only)
    float xr = 0.f, xz = 0.f, xn = 0.f;
    if (tid < 64) {
        xr = xbase[j0 + tid];
        xz = xbase[256 + j0 + tid];
        xn = xbase[512 + j0 + tid];
    }

    for (int t = 0; t < T_STEPS; t++) {
        const int par = t & 1;

        // ---- matvec: this thread's 128-k half of its gate row ----
        ull acc0 = 0ull, acc1 = 0ull;
        const float4* h4 = (const float4*)hbuf[par] + hf * 32;
        #pragma unroll
        for (int i = 0; i < 32; i++) {
            union { float4 f; ull u[2]; } hv;
            hv.f = h4[i];
            ffma2(acc0, w[2 * i],     hv.u[0]);
            ffma2(acc1, w[2 * i + 1], hv.u[1]);
        }
        union { ull u; float f[2]; } ua, ub;
        ua.u = acc0; ub.u = acc1;
        float s = (ua.f[0] + ua.f[1]) + (ub.f[0] + ub.f[1]);
        s += __shfl_xor_sync(0xffffffffu, s, 1);   // combine the two k-halves
        if (hf == 0) gsum[ro] = s;
        __syncthreads();

        // ---- epilogue: 64 threads finalize their hidden units ----
        float hnew = 0.f;
        if (tid < 64) {
            const int j = tid;
            float r = sigmoid_fast(gsum[j]      + bhr + xr);
            float z = sigmoid_fast(gsum[64 + j] + bhz + xz);
            float n = tanh_fast(fmaf(r, gsum[128 + j] + bhn, xn));
            float hold = hbuf[par][j0 + j];
            hnew = fmaf(z, hold - n, n);            // (1-z)*n + z*h

            // pack (even, odd) unit pair; split the 4-rank fan-out across
            // the pair: even tid -> ranks 0,1 ; odd tid -> ranks 2,3
            float hp = __shfl_xor_sync(0xffffffffu, hnew, 1);
            union { float f[2]; ull u; } pk;
            if ((j & 1) == 0) { pk.f[0] = hnew; pk.f[1] = hp; }
            else              { pk.f[0] = hp;   pk.f[1] = hnew; }
            uint32_t laddr = hb0 + (uint32_t)(par ^ 1) * 1024u
                           + (uint32_t)(j0 + (j & ~1)) * 4u;
            uint32_t r0 = (j & 1) ? 2u : 0u;
            st_cluster_b64(laddr, r0,      pk.u);
            st_cluster_b64(laddr, r0 + 1u, pk.u);
        }

        // arrive releases ONLY the remote sends (and prior smem traffic);
        // the DRAM store + prefetch below run in the wait shadow.
        asm volatile("barrier.cluster.arrive.aligned;" ::: "memory");

        if (tid < 64) {
            obase[(size_t)t * HID + j0 + tid] = hnew;
            if (write_hn && t == T_STEPS - 1)
                out[(size_t)BATCH * T_STEPS * HID + (size_t)b * HID + j0 + tid] = hnew;
            const int tn = (t + 1 < T_STEPS) ? (t + 1) : (T_STEPS - 1);
            const float* p = xbase + (size_t)tn * GCOLS;
            xr = p[j0 + tid]; xz = p[256 + j0 + tid]; xn = p[512 + j0 + tid];
        }

        asm volatile("barrier.cluster.wait.aligned;"  ::: "memory");
    }
}

// ---------------------------------------------------------------------------
// launch
// ---------------------------------------------------------------------------
extern "C" void kernel_launch(void* const* d_in, const int* in_sizes, int n_in,
                              void* d_out, int out_size)
{
    (void)in_sizes; (void)n_in;
    const float* x     = (const float*)d_in[0];
    const float* h0    = (const float*)d_in[1];
    const float* W_irz = (const float*)d_in[2];
    const float* b_irz = (const float*)d_in[3];
    const float* W_hrz = (const float*)d_in[4];
    const float* b_hrz = (const float*)d_in[5];
    const float* W_in  = (const float*)d_in[6];
    const float* b_in  = (const float*)d_in[7];
    const float* W_hn  = (const float*)d_in[8];
    const float* b_hn  = (const float*)d_in[9];
    float* out = (float*)d_out;

    cudaFuncSetAttribute(proj_kernel, cudaFuncAttributeMaxDynamicSharedMemorySize,
                         PROJ_SMEM_BYTES);
    cudaFuncSetAttribute(gru_kernel, cudaFuncAttributeNonPortableClusterSizeAllowed, 1);

    proj_kernel<<<dim3(BT / 64, GCOLS / 128, 1), 128, PROJ_SMEM_BYTES>>>(
        x, W_irz, b_irz, W_in, b_in);

    const long long need_hn = (long long)BATCH * T_STEPS * HID + (long long)BATCH * HID;
    int write_hn = ((long long)out_size >= need_hn) ? 1 : 0;
    gru_kernel<<<BATCH * 4, 384>>>(h0, W_hrz, b_hrz, W_hn, b_hn, out, write_hn);
}